// round 16
// baseline (speedup 1.0000x reference)
#include <cuda_runtime.h>
#include <cuda_fp16.h>
#include <math.h>
#include <float.h>
#include <stdint.h>

// Problem constants (fixed by dataset)
#define E_EDGES   1600000
#define N_NODES   50000
#define D_IN      128
#define D_OUT     128
#define K_GEMM    512          // 4 stats * 128
#define EPS_STD   1e-5f
#define EPS_BN    1e-5f

#define SCAN_BLK  1024
#define SCAN_NBLK ((N_NODES + SCAN_BLK - 1) / SCAN_BLK)   // 49
#define GEMM_TILES ((N_NODES + 127) / 128)                // 391

#define WLO_SCALE 64.0f
#define H2_INV64  0x24002400u    // half2(2^-6, 2^-6)

// ------------------------- device scratch --------------------------------
__device__ int   g_counts[N_NODES];
__device__ int   g_offsets[N_NODES + 1];
__device__ int   g_cursor[N_NODES];
__device__ int   g_deg[N_NODES];
__device__ int   g_perm[E_EDGES];
__device__ int   g_agg[SCAN_NBLK];
__device__ __half g_xh[(size_t)N_NODES * K_GEMM];   // aggregated feats (fp16)
__device__ __half g_wt_hi[D_OUT * K_GEMM];          // W[0:512]^T hi  [n][k]
__device__ __half g_wt_lo[D_OUT * K_GEMM];          // (W - Whi)^T * 2^6
__device__ float g_degW[100 * D_OUT];
__device__ float g_colsum[D_OUT];
__device__ float g_colsq[D_OUT];

// ------------------------- histogram (int4 vectorized) --------------------
__global__ void k_hist(const int* __restrict__ index) {
    int i = blockIdx.x * blockDim.x + threadIdx.x;
    if (i < E_EDGES / 4) {
        int4 v = __ldg((const int4*)index + i);
        atomicAdd(&g_counts[v.x], 1);
        atomicAdd(&g_counts[v.y], 1);
        atomicAdd(&g_counts[v.z], 1);
        atomicAdd(&g_counts[v.w], 1);
    }
}

// ------------------------- single-pass scan (publish + parallel lookback) --
__global__ __launch_bounds__(1024) void k_scan_onepass() {
    __shared__ int wsum[32];
    __shared__ int s_prefix;
    int b = blockIdx.x;
    int t = threadIdx.x, lane = t & 31, w = t >> 5;
    int i = b * SCAN_BLK + t;
    int v = (i < N_NODES) ? g_counts[i] : 0;

    int x = v;
    #pragma unroll
    for (int o = 1; o < 32; o <<= 1) {
        int y = __shfl_up_sync(0xffffffffu, x, o);
        if (lane >= o) x += y;
    }
    if (lane == 31) wsum[w] = x;
    __syncthreads();
    if (w == 0) {
        int y = wsum[lane];
        #pragma unroll
        for (int o = 1; o < 32; o <<= 1) {
            int z = __shfl_up_sync(0xffffffffu, y, o);
            if (lane >= o) y += z;
        }
        wsum[lane] = y;
    }
    __syncthreads();
    int wp = (w == 0) ? 0 : wsum[w - 1];
    int incl = x + wp;
    int T = wsum[31];

    if (t == 0) atomicExch(&g_agg[b], T + 1);

    if (w == 0) {
        int sum = 0;
        for (int j = lane; j < b; j += 32) {
            int a;
            do { a = ((volatile int*)g_agg)[j]; } while (a == 0);
            sum += a - 1;
        }
        #pragma unroll
        for (int o = 16; o > 0; o >>= 1)
            sum += __shfl_xor_sync(0xffffffffu, sum, o);
        if (lane == 0) s_prefix = sum;
    }
    __syncthreads();

    int excl = incl - v + s_prefix;
    if (i < N_NODES) {
        g_offsets[i] = excl;
        g_cursor[i]  = excl;
    }
    if (i == 0) g_offsets[N_NODES] = E_EDGES;
}

// ------------------------- scatter (int4, 4 edges/thread) ------------------
__global__ void k_scatter(const int* __restrict__ index) {
    int i = blockIdx.x * blockDim.x + threadIdx.x;
    if (i < E_EDGES / 4) {
        int4 v = __ldg((const int4*)index + i);
        int e = i * 4;
        g_perm[atomicAdd(&g_cursor[v.x], 1)] = e;
        g_perm[atomicAdd(&g_cursor[v.y], 1)] = e + 1;
        g_perm[atomicAdd(&g_cursor[v.z], 1)] = e + 2;
        g_perm[atomicAdd(&g_cursor[v.w], 1)] = e + 3;
    }
}

// ------------------------- per-node aggregation (warp per node, unroll 8) --
__global__ __launch_bounds__(256) void k_agg(const float* __restrict__ inputs) {
    int n = blockIdx.x * 8 + (threadIdx.x >> 5);
    int lane = threadIdx.x & 31;
    if (n >= N_NODES) return;

    int start = g_offsets[n];
    int end   = g_offsets[n + 1];
    int cnt   = end - start;

    float4 s  = make_float4(0.f, 0.f, 0.f, 0.f);
    float4 sq = make_float4(0.f, 0.f, 0.f, 0.f);
    float4 mn = make_float4(FLT_MAX, FLT_MAX, FLT_MAX, FLT_MAX);
    float4 mx = make_float4(-FLT_MAX, -FLT_MAX, -FLT_MAX, -FLT_MAX);

    const float4* inp4 = (const float4*)inputs;

    int base = start;
    while (base + 32 <= end) {
        int p = g_perm[base + lane];
        #pragma unroll 8
        for (int j = 0; j < 32; j++) {
            int e = __shfl_sync(0xffffffffu, p, j);
            float4 v = __ldg(inp4 + (size_t)e * 32 + lane);
            s.x += v.x;  s.y += v.y;  s.z += v.z;  s.w += v.w;
            sq.x = fmaf(v.x, v.x, sq.x); sq.y = fmaf(v.y, v.y, sq.y);
            sq.z = fmaf(v.z, v.z, sq.z); sq.w = fmaf(v.w, v.w, sq.w);
            mn.x = fminf(mn.x, v.x); mn.y = fminf(mn.y, v.y);
            mn.z = fminf(mn.z, v.z); mn.w = fminf(mn.w, v.w);
            mx.x = fmaxf(mx.x, v.x); mx.y = fmaxf(mx.y, v.y);
            mx.z = fmaxf(mx.z, v.z); mx.w = fmaxf(mx.w, v.w);
        }
        base += 32;
    }
    int rem = end - base;
    if (rem > 0) {
        int p = (lane < rem) ? g_perm[base + lane] : 0;
        for (int j = 0; j < rem; j++) {
            int e = __shfl_sync(0xffffffffu, p, j);
            float4 v = __ldg(inp4 + (size_t)e * 32 + lane);
            s.x += v.x;  s.y += v.y;  s.z += v.z;  s.w += v.w;
            sq.x = fmaf(v.x, v.x, sq.x); sq.y = fmaf(v.y, v.y, sq.y);
            sq.z = fmaf(v.z, v.z, sq.z); sq.w = fmaf(v.w, v.w, sq.w);
            mn.x = fminf(mn.x, v.x); mn.y = fminf(mn.y, v.y);
            mn.z = fminf(mn.z, v.z); mn.w = fminf(mn.w, v.w);
            mx.x = fmaxf(mx.x, v.x); mx.y = fmaxf(mx.y, v.y);
            mx.z = fmaxf(mx.z, v.z); mx.w = fmaxf(mx.w, v.w);
        }
    }

    float safe = fmaxf((float)cnt, 1.f);
    float inv  = 1.f / safe;
    float4 mean, stdv;
    mean.x = s.x * inv; mean.y = s.y * inv; mean.z = s.z * inv; mean.w = s.w * inv;
    stdv.x = sqrtf(fmaxf(sq.x * inv - mean.x * mean.x, 0.f) + EPS_STD);
    stdv.y = sqrtf(fmaxf(sq.y * inv - mean.y * mean.y, 0.f) + EPS_STD);
    stdv.z = sqrtf(fmaxf(sq.z * inv - mean.z * mean.z, 0.f) + EPS_STD);
    stdv.w = sqrtf(fmaxf(sq.w * inv - mean.w * mean.w, 0.f) + EPS_STD);
    if (cnt == 0) {
        mn = make_float4(0.f, 0.f, 0.f, 0.f);
        mx = make_float4(0.f, 0.f, 0.f, 0.f);
    }

    size_t rb = (size_t)n * K_GEMM;
    float4 vals[4] = { mean, mn, mx, stdv };
    #pragma unroll
    for (int q = 0; q < 4; q++) {
        __half h0 = __float2half(vals[q].x);
        __half h1 = __float2half(vals[q].y);
        __half h2 = __float2half(vals[q].z);
        __half h3 = __float2half(vals[q].w);
        uint32_t u01 = (uint32_t)__half_as_ushort(h0) | ((uint32_t)__half_as_ushort(h1) << 16);
        uint32_t u23 = (uint32_t)__half_as_ushort(h2) | ((uint32_t)__half_as_ushort(h3) << 16);
        *(uint2*)(g_xh + rb + q * 128 + lane * 4) = make_uint2(u01, u23);
    }
    if (lane == 0) g_deg[n] = min(cnt, 99);
}

// ------------------------- merged prep: degW + W transpose/split ----------
__global__ void k_prep(const float* __restrict__ deg_emb, const float* __restrict__ W) {
    int t = threadIdx.x;
    if (blockIdx.x < 100) {
        int d = blockIdx.x;
        __shared__ float e[D_IN];
        e[t] = deg_emb[d * D_IN + t];
        __syncthreads();
        float acc = 0.f;
        #pragma unroll 8
        for (int k = 0; k < D_IN; k++)
            acc = fmaf(e[k], W[(size_t)(K_GEMM + k) * D_OUT + t], acc);
        g_degW[d * D_OUT + t] = acc;
    } else {
        int n = blockIdx.x - 100;
        #pragma unroll
        for (int q = 0; q < 4; q++) {
            int k = q * 128 + t;
            float v = W[(size_t)k * D_OUT + n];
            __half hi = __float2half(v);
            float lo = (v - __half2float(hi)) * WLO_SCALE;
            g_wt_hi[(size_t)n * K_GEMM + k] = hi;
            g_wt_lo[(size_t)n * K_GEMM + k] = __float2half(lo);
        }
    }
}

// ------------------------- tensor-core GEMM (fp16 2-term, GBK=64) ----------
#define GBK     64
#define GAPITCH 72                          // f16 elems per smem row (64+8 pad)
#define TILE_B  (128 * GAPITCH * 2)         // 18432 bytes
#define STAGE_B (3 * TILE_B)                // A | Bhi | Blo = 55296
#define SM_A    0
#define SM_BH   (TILE_B)
#define SM_BL   (2 * TILE_B)
#define SM_GEMM_TOTAL (2 * STAGE_B)         // 110592
#define NCHUNK  (K_GEMM / GBK)              // 8

__device__ __forceinline__ uint32_t smem_u32(const void* p) {
    uint32_t a;
    asm("{ .reg .u64 t; cvta.to.shared.u64 t, %1; cvt.u32.u64 %0, t; }" : "=r"(a) : "l"(p));
    return a;
}
__device__ __forceinline__ void cp16(uint32_t dst, const void* src, int ok) {
    asm volatile("cp.async.cg.shared.global [%0], [%1], 16, %2;"
                 :: "r"(dst), "l"(src), "r"(ok ? 16 : 0) : "memory");
}
__device__ __forceinline__ void ldm_x4(uint32_t& r0, uint32_t& r1, uint32_t& r2, uint32_t& r3,
                                       uint32_t addr) {
    asm volatile("ldmatrix.sync.aligned.m8n8.x4.shared.b16 {%0,%1,%2,%3}, [%4];"
                 : "=r"(r0), "=r"(r1), "=r"(r2), "=r"(r3) : "r"(addr));
}
__device__ __forceinline__ void ldm_x2(uint32_t& r0, uint32_t& r1, uint32_t addr) {
    asm volatile("ldmatrix.sync.aligned.m8n8.x2.shared.b16 {%0,%1}, [%2];"
                 : "=r"(r0), "=r"(r1) : "r"(addr));
}
__device__ __forceinline__ uint32_t hmul2c(uint32_t a, uint32_t s) {
    uint32_t r;
    asm("mul.f16x2 %0, %1, %2;" : "=r"(r) : "r"(a), "r"(s));
    return r;
}
__device__ __forceinline__ void mma_f16(float* c, uint32_t a0, uint32_t a1, uint32_t a2,
                                        uint32_t a3, uint32_t b0, uint32_t b1) {
    asm volatile(
        "mma.sync.aligned.m16n8k16.row.col.f32.f16.f16.f32 "
        "{%0,%1,%2,%3}, {%4,%5,%6,%7}, {%8,%9}, {%0,%1,%2,%3};"
        : "+f"(c[0]), "+f"(c[1]), "+f"(c[2]), "+f"(c[3])
        : "r"(a0), "r"(a1), "r"(a2), "r"(a3), "r"(b0), "r"(b1));
}

__global__ __launch_bounds__(256, 2) void k_gemm_mma(float* __restrict__ out) {
    extern __shared__ char smem[];
    uint32_t sbase = smem_u32(smem);

    int t    = threadIdx.x;
    int wid  = t >> 5;
    int lane = t & 31;
    int warp_m = wid >> 2;
    int warp_n = wid & 3;
    int bm = blockIdx.x * 128;

    float acc[4][4][4];
    #pragma unroll
    for (int i = 0; i < 4; i++)
        #pragma unroll
        for (int j = 0; j < 4; j++)
            #pragma unroll
            for (int q = 0; q < 4; q++) acc[i][j][q] = 0.f;

    int a_row = warp_m * 64 + (lane & 15);
    int a_kof = (lane >> 4) * 8;
    int b_row = warp_n * 32 + (lane & 7);
    int b_kof = ((lane >> 3) & 1) * 8;

    const char* xh = (const char*)(g_xh + (size_t)bm * K_GEMM);

    int lr[4], lu[4], okA[4];
    #pragma unroll
    for (int p = 0; p < 4; p++) {
        int u = t + p * 256;
        lr[p] = u >> 3;
        lu[p] = u & 7;
        okA[p] = (bm + lr[p]) < N_NODES;
    }

    #define ISSUE(c, st) do {                                                   \
        uint32_t sbuf = sbase + (st) * STAGE_B;                                  \
        _Pragma("unroll")                                                        \
        for (int p = 0; p < 4; p++) {                                            \
            size_t go = ((size_t)lr[p] * K_GEMM + (c) * GBK + lu[p] * 8) * 2;    \
            uint32_t so = (uint32_t)lr[p] * (GAPITCH * 2) + lu[p] * 16;          \
            cp16(sbuf + SM_A  + so, xh + go, okA[p]);                            \
            cp16(sbuf + SM_BH + so, (const char*)g_wt_hi + go, 1);               \
            cp16(sbuf + SM_BL + so, (const char*)g_wt_lo + go, 1);               \
        }                                                                        \
        asm volatile("cp.async.commit_group;" ::: "memory");                     \
    } while (0)

    ISSUE(0, 0);

    for (int c = 0; c < NCHUNK; c++) {
        int st = c & 1;
        if (c + 1 < NCHUNK) {
            ISSUE(c + 1, st ^ 1);
            asm volatile("cp.async.wait_group 1;" ::: "memory");
        } else {
            asm volatile("cp.async.wait_group 0;" ::: "memory");
        }
        __syncthreads();

        uint32_t sb = sbase + st * STAGE_B;
        #pragma unroll
        for (int ks = 0; ks < GBK / 16; ks++) {
            uint32_t bh[4][2], bl[4][2];
            #pragma unroll
            for (int nj = 0; nj < 4; nj++) {
                uint32_t bofs = (uint32_t)(b_row + nj * 8) * (GAPITCH * 2)
                              + (ks * 16 + b_kof) * 2;
                ldm_x2(bh[nj][0], bh[nj][1], sb + SM_BH + bofs);
                ldm_x2(bl[nj][0], bl[nj][1], sb + SM_BL + bofs);
                bl[nj][0] = hmul2c(bl[nj][0], H2_INV64);
                bl[nj][1] = hmul2c(bl[nj][1], H2_INV64);
            }
            uint32_t ah[4][4];
            #pragma unroll
            for (int mi = 0; mi < 4; mi++) {
                uint32_t aofs = (uint32_t)(a_row + mi * 16) * (GAPITCH * 2)
                              + (ks * 16 + a_kof) * 2;
                ldm_x4(ah[mi][0], ah[mi][1], ah[mi][2], ah[mi][3], sb + SM_A + aofs);
            }
            // sweep 1: Xh * Whi
            #pragma unroll
            for (int mi = 0; mi < 4; mi++)
                #pragma unroll
                for (int nj = 0; nj < 4; nj++)
                    mma_f16(acc[mi][nj], ah[mi][0], ah[mi][1], ah[mi][2], ah[mi][3],
                            bh[nj][0], bh[nj][1]);
            // sweep 2: Xh * Wlo
            #pragma unroll
            for (int mi = 0; mi < 4; mi++)
                #pragma unroll
                for (int nj = 0; nj < 4; nj++)
                    mma_f16(acc[mi][nj], ah[mi][0], ah[mi][1], ah[mi][2], ah[mi][3],
                            bl[nj][0], bl[nj][1]);
        }
        __syncthreads();
    }

    // ---- epilogue: + degW, store, BN column partials ----
    float* scol  = (float*)smem;
    float* scolq = (float*)(smem + 512);
    if (t < 128) { scol[t] = 0.f; scolq[t] = 0.f; }
    __syncthreads();

    int gid = lane >> 2;
    int tig = lane & 3;
    float ls[8], lq[8];
    #pragma unroll
    for (int q = 0; q < 8; q++) { ls[q] = 0.f; lq[q] = 0.f; }

    #pragma unroll
    for (int mi = 0; mi < 4; mi++) {
        #pragma unroll
        for (int half = 0; half < 2; half++) {
            int row = bm + warp_m * 64 + mi * 16 + gid + half * 8;
            if (row < N_NODES) {
                int dg = g_deg[row];
                const float* dw = &g_degW[dg * D_OUT];
                #pragma unroll
                for (int nj = 0; nj < 4; nj++) {
                    int col = warp_n * 32 + nj * 8 + tig * 2;
                    float2 v;
                    v.x = acc[mi][nj][half * 2 + 0] + dw[col];
                    v.y = acc[mi][nj][half * 2 + 1] + dw[col + 1];
                    *(float2*)&out[(size_t)row * D_OUT + col] = v;
                    ls[nj * 2 + 0] += v.x;  lq[nj * 2 + 0] = fmaf(v.x, v.x, lq[nj * 2 + 0]);
                    ls[nj * 2 + 1] += v.y;  lq[nj * 2 + 1] = fmaf(v.y, v.y, lq[nj * 2 + 1]);
                }
            }
        }
    }
    #pragma unroll
    for (int nj = 0; nj < 4; nj++) {
        #pragma unroll
        for (int xy = 0; xy < 2; xy++) {
            int col = warp_n * 32 + nj * 8 + tig * 2 + xy;
            atomicAdd(&scol[col],  ls[nj * 2 + xy]);
            atomicAdd(&scolq[col], lq[nj * 2 + xy]);
        }
    }
    __syncthreads();
    if (t < 128) {
        atomicAdd(&g_colsum[t], scol[t]);
        atomicAdd(&g_colsq[t],  scolq[t]);
    }
}

// ------------------------- fused BN finalize + normalize -------------------
__global__ __launch_bounds__(256) void k_normalize(const float* __restrict__ gamma,
                                                   const float* __restrict__ beta,
                                                   float* __restrict__ out) {
    __shared__ float sscale[128], sbias[128];
    if (threadIdx.x < 128) {
        int c = threadIdx.x;
        float inv_n = 1.f / (float)N_NODES;
        float mu  = g_colsum[c] * inv_n;
        float var = g_colsq[c] * inv_n - mu * mu;
        float rstd = rsqrtf(var + EPS_BN);
        float sc = gamma[c] * rstd;
        sscale[c] = sc;
        sbias[c]  = beta[c] - mu * sc;
    }
    __syncthreads();
    int i = blockIdx.x * blockDim.x + threadIdx.x;
    if (i < N_NODES * D_OUT / 4) {
        int c0 = (i & 31) * 4;
        float4 v = ((float4*)out)[i];
        v.x = fmaxf(0.f, fmaf(v.x, sscale[c0 + 0], sbias[c0 + 0]));
        v.y = fmaxf(0.f, fmaf(v.y, sscale[c0 + 1], sbias[c0 + 1]));
        v.z = fmaxf(0.f, fmaf(v.z, sscale[c0 + 2], sbias[c0 + 2]));
        v.w = fmaxf(0.f, fmaf(v.w, sscale[c0 + 3], sbias[c0 + 3]));
        ((float4*)out)[i] = v;
    }
}

// ------------------------- launch -----------------------------------------
extern "C" void kernel_launch(void* const* d_in, const int* in_sizes, int n_in,
                              void* d_out, int out_size) {
    const float* inputs  = (const float*)d_in[0];   // [E, 128]
    const int*   index   = (const int*)  d_in[1];   // [E]
    const float* deg_emb = (const float*)d_in[2];   // [100, 128]
    const float* W       = (const float*)d_in[3];   // [640, 128]
    const float* gamma   = (const float*)d_in[4];   // [128]
    const float* beta    = (const float*)d_in[5];   // [128]
    float* out = (float*)d_out;                     // [50000, 128]

    static cudaStream_t s2 = nullptr;
    static cudaEvent_t ev_fork, ev_prep;
    if (!s2) {
        cudaStreamCreateWithFlags(&s2, cudaStreamNonBlocking);
        cudaEventCreateWithFlags(&ev_fork, cudaEventDisableTiming);
        cudaEventCreateWithFlags(&ev_prep, cudaEventDisableTiming);
        cudaFuncSetAttribute(k_gemm_mma, cudaFuncAttributeMaxDynamicSharedMemorySize,
                             SM_GEMM_TOTAL);
    }

    void* p_counts = nullptr; void* p_colsum = nullptr; void* p_colsq = nullptr;
    void* p_agg = nullptr;
    cudaGetSymbolAddress(&p_counts, g_counts);
    cudaGetSymbolAddress(&p_colsum, g_colsum);
    cudaGetSymbolAddress(&p_colsq,  g_colsq);
    cudaGetSymbolAddress(&p_agg,    g_agg);

    // fork: prep work (memsets + W split/degW) overlaps the CSR build
    cudaEventRecord(ev_fork, 0);
    cudaStreamWaitEvent(s2, ev_fork, 0);
    cudaMemsetAsync(p_colsum, 0, D_OUT * sizeof(float), s2);
    cudaMemsetAsync(p_colsq,  0, D_OUT * sizeof(float), s2);
    k_prep<<<228, 128, 0, s2>>>(deg_emb, W);
    cudaEventRecord(ev_prep, s2);

    // main stream: CSR build + aggregation
    cudaMemsetAsync(p_counts, 0, N_NODES * sizeof(int));
    cudaMemsetAsync(p_agg,    0, SCAN_NBLK * sizeof(int));
    k_hist<<<(E_EDGES / 4 + 255) / 256, 256>>>(index);
    k_scan_onepass<<<SCAN_NBLK, SCAN_BLK>>>();
    k_scatter<<<(E_EDGES / 4 + 255) / 256, 256>>>(index);
    k_agg<<<(N_NODES + 7) / 8, 256>>>(inputs);

    // join: GEMM needs prep outputs
    cudaStreamWaitEvent(0, ev_prep, 0);
    k_gemm_mma<<<GEMM_TILES, 256, SM_GEMM_TOTAL>>>(out);
    k_normalize<<<(N_NODES * D_OUT / 4 + 255) / 256, 256>>>(gamma, beta, out);
}

// round 17
// speedup vs baseline: 1.0185x; 1.0185x over previous
#include <cuda_runtime.h>
#include <cuda_fp16.h>
#include <math.h>
#include <float.h>
#include <stdint.h>

// Problem constants (fixed by dataset)
#define E_EDGES   1600000
#define N_NODES   50000
#define D_IN      128
#define D_OUT     128
#define K_GEMM    512          // 4 stats * 128
#define EPS_STD   1e-5f
#define EPS_BN    1e-5f

#define SCAN_BLK  1024
#define SCAN_NBLK ((N_NODES + SCAN_BLK - 1) / SCAN_BLK)   // 49
#define GEMM_TILES ((N_NODES + 127) / 128)                // 391

#define WLO_SCALE 64.0f
#define H2_INV64  0x24002400u    // half2(2^-6, 2^-6)

// ------------------------- device scratch --------------------------------
__device__ int   g_counts[N_NODES];
__device__ int   g_offsets[N_NODES + 1];
__device__ int   g_cursor[N_NODES];
__device__ int   g_deg[N_NODES];
__device__ int   g_perm[E_EDGES];
__device__ int   g_agg[SCAN_NBLK];
__device__ __half g_xh[(size_t)N_NODES * K_GEMM];   // aggregated feats (fp16)
__device__ __half g_wt_hi[D_OUT * K_GEMM];          // W[0:512]^T hi  [n][k]
__device__ __half g_wt_lo[D_OUT * K_GEMM];          // (W - Whi)^T * 2^6
__device__ float g_degW[100 * D_OUT];
__device__ float g_colsum[D_OUT];
__device__ float g_colsq[D_OUT];

// ------------------------- histogram (int4 vectorized) --------------------
__global__ void k_hist(const int* __restrict__ index) {
    int i = blockIdx.x * blockDim.x + threadIdx.x;
    if (i < E_EDGES / 4) {
        int4 v = __ldg((const int4*)index + i);
        atomicAdd(&g_counts[v.x], 1);
        atomicAdd(&g_counts[v.y], 1);
        atomicAdd(&g_counts[v.z], 1);
        atomicAdd(&g_counts[v.w], 1);
    }
}

// ------------------------- single-pass scan (publish + parallel lookback) --
__global__ __launch_bounds__(1024) void k_scan_onepass() {
    __shared__ int wsum[32];
    __shared__ int s_prefix;
    int b = blockIdx.x;
    int t = threadIdx.x, lane = t & 31, w = t >> 5;
    int i = b * SCAN_BLK + t;
    int v = (i < N_NODES) ? g_counts[i] : 0;

    int x = v;
    #pragma unroll
    for (int o = 1; o < 32; o <<= 1) {
        int y = __shfl_up_sync(0xffffffffu, x, o);
        if (lane >= o) x += y;
    }
    if (lane == 31) wsum[w] = x;
    __syncthreads();
    if (w == 0) {
        int y = wsum[lane];
        #pragma unroll
        for (int o = 1; o < 32; o <<= 1) {
            int z = __shfl_up_sync(0xffffffffu, y, o);
            if (lane >= o) y += z;
        }
        wsum[lane] = y;
    }
    __syncthreads();
    int wp = (w == 0) ? 0 : wsum[w - 1];
    int incl = x + wp;
    int T = wsum[31];

    if (t == 0) atomicExch(&g_agg[b], T + 1);

    if (w == 0) {
        int sum = 0;
        for (int j = lane; j < b; j += 32) {
            int a;
            do { a = ((volatile int*)g_agg)[j]; } while (a == 0);
            sum += a - 1;
        }
        #pragma unroll
        for (int o = 16; o > 0; o >>= 1)
            sum += __shfl_xor_sync(0xffffffffu, sum, o);
        if (lane == 0) s_prefix = sum;
    }
    __syncthreads();

    int excl = incl - v + s_prefix;
    if (i < N_NODES) {
        g_offsets[i] = excl;
        g_cursor[i]  = excl;
    }
    if (i == 0) g_offsets[N_NODES] = E_EDGES;
}

// ------------------------- scatter (int4, 4 edges/thread) ------------------
__global__ void k_scatter(const int* __restrict__ index) {
    int i = blockIdx.x * blockDim.x + threadIdx.x;
    if (i < E_EDGES / 4) {
        int4 v = __ldg((const int4*)index + i);
        int e = i * 4;
        g_perm[atomicAdd(&g_cursor[v.x], 1)] = e;
        g_perm[atomicAdd(&g_cursor[v.y], 1)] = e + 1;
        g_perm[atomicAdd(&g_cursor[v.z], 1)] = e + 2;
        g_perm[atomicAdd(&g_cursor[v.w], 1)] = e + 3;
    }
}

// ------------------------- per-node aggregation (warp per node, unroll 4) --
__global__ __launch_bounds__(256) void k_agg(const float* __restrict__ inputs) {
    int n = blockIdx.x * 8 + (threadIdx.x >> 5);
    int lane = threadIdx.x & 31;
    if (n >= N_NODES) return;

    int start = g_offsets[n];
    int end   = g_offsets[n + 1];
    int cnt   = end - start;

    float4 s  = make_float4(0.f, 0.f, 0.f, 0.f);
    float4 sq = make_float4(0.f, 0.f, 0.f, 0.f);
    float4 mn = make_float4(FLT_MAX, FLT_MAX, FLT_MAX, FLT_MAX);
    float4 mx = make_float4(-FLT_MAX, -FLT_MAX, -FLT_MAX, -FLT_MAX);

    const float4* inp4 = (const float4*)inputs;

    int base = start;
    while (base + 32 <= end) {
        int p = g_perm[base + lane];
        #pragma unroll 4
        for (int j = 0; j < 32; j++) {
            int e = __shfl_sync(0xffffffffu, p, j);
            float4 v = __ldg(inp4 + (size_t)e * 32 + lane);
            s.x += v.x;  s.y += v.y;  s.z += v.z;  s.w += v.w;
            sq.x = fmaf(v.x, v.x, sq.x); sq.y = fmaf(v.y, v.y, sq.y);
            sq.z = fmaf(v.z, v.z, sq.z); sq.w = fmaf(v.w, v.w, sq.w);
            mn.x = fminf(mn.x, v.x); mn.y = fminf(mn.y, v.y);
            mn.z = fminf(mn.z, v.z); mn.w = fminf(mn.w, v.w);
            mx.x = fmaxf(mx.x, v.x); mx.y = fmaxf(mx.y, v.y);
            mx.z = fmaxf(mx.z, v.z); mx.w = fmaxf(mx.w, v.w);
        }
        base += 32;
    }
    int rem = end - base;
    if (rem > 0) {
        int p = (lane < rem) ? g_perm[base + lane] : 0;
        #pragma unroll 4
        for (int j = 0; j < rem; j++) {
            int e = __shfl_sync(0xffffffffu, p, j);
            float4 v = __ldg(inp4 + (size_t)e * 32 + lane);
            s.x += v.x;  s.y += v.y;  s.z += v.z;  s.w += v.w;
            sq.x = fmaf(v.x, v.x, sq.x); sq.y = fmaf(v.y, v.y, sq.y);
            sq.z = fmaf(v.z, v.z, sq.z); sq.w = fmaf(v.w, v.w, sq.w);
            mn.x = fminf(mn.x, v.x); mn.y = fminf(mn.y, v.y);
            mn.z = fminf(mn.z, v.z); mn.w = fminf(mn.w, v.w);
            mx.x = fmaxf(mx.x, v.x); mx.y = fmaxf(mx.y, v.y);
            mx.z = fmaxf(mx.z, v.z); mx.w = fmaxf(mx.w, v.w);
        }
    }

    float safe = fmaxf((float)cnt, 1.f);
    float inv  = 1.f / safe;
    float4 mean, stdv;
    mean.x = s.x * inv; mean.y = s.y * inv; mean.z = s.z * inv; mean.w = s.w * inv;
    stdv.x = sqrtf(fmaxf(sq.x * inv - mean.x * mean.x, 0.f) + EPS_STD);
    stdv.y = sqrtf(fmaxf(sq.y * inv - mean.y * mean.y, 0.f) + EPS_STD);
    stdv.z = sqrtf(fmaxf(sq.z * inv - mean.z * mean.z, 0.f) + EPS_STD);
    stdv.w = sqrtf(fmaxf(sq.w * inv - mean.w * mean.w, 0.f) + EPS_STD);
    if (cnt == 0) {
        mn = make_float4(0.f, 0.f, 0.f, 0.f);
        mx = make_float4(0.f, 0.f, 0.f, 0.f);
    }

    size_t rb = (size_t)n * K_GEMM;
    float4 vals[4] = { mean, mn, mx, stdv };
    #pragma unroll
    for (int q = 0; q < 4; q++) {
        __half h0 = __float2half(vals[q].x);
        __half h1 = __float2half(vals[q].y);
        __half h2 = __float2half(vals[q].z);
        __half h3 = __float2half(vals[q].w);
        uint32_t u01 = (uint32_t)__half_as_ushort(h0) | ((uint32_t)__half_as_ushort(h1) << 16);
        uint32_t u23 = (uint32_t)__half_as_ushort(h2) | ((uint32_t)__half_as_ushort(h3) << 16);
        *(uint2*)(g_xh + rb + q * 128 + lane * 4) = make_uint2(u01, u23);
    }
    if (lane == 0) g_deg[n] = min(cnt, 99);
}

// ------------------------- merged prep: degW + W transpose/split ----------
__global__ void k_prep(const float* __restrict__ deg_emb, const float* __restrict__ W) {
    int t = threadIdx.x;
    if (blockIdx.x < 100) {
        int d = blockIdx.x;
        __shared__ float e[D_IN];
        e[t] = deg_emb[d * D_IN + t];
        __syncthreads();
        float acc = 0.f;
        #pragma unroll 8
        for (int k = 0; k < D_IN; k++)
            acc = fmaf(e[k], W[(size_t)(K_GEMM + k) * D_OUT + t], acc);
        g_degW[d * D_OUT + t] = acc;
    } else {
        int n = blockIdx.x - 100;
        #pragma unroll
        for (int q = 0; q < 4; q++) {
            int k = q * 128 + t;
            float v = W[(size_t)k * D_OUT + n];
            __half hi = __float2half(v);
            float lo = (v - __half2float(hi)) * WLO_SCALE;
            g_wt_hi[(size_t)n * K_GEMM + k] = hi;
            g_wt_lo[(size_t)n * K_GEMM + k] = __float2half(lo);
        }
    }
}

// ------------------------- tensor-core GEMM (fp16 2-term, GBK=64) ----------
#define GBK     64
#define GAPITCH 72                          // f16 elems per smem row (64+8 pad)
#define TILE_B  (128 * GAPITCH * 2)         // 18432 bytes
#define STAGE_B (3 * TILE_B)                // A | Bhi | Blo = 55296
#define SM_A    0
#define SM_BH   (TILE_B)
#define SM_BL   (2 * TILE_B)
#define SM_GEMM_TOTAL (2 * STAGE_B)         // 110592
#define NCHUNK  (K_GEMM / GBK)              // 8

__device__ __forceinline__ uint32_t smem_u32(const void* p) {
    uint32_t a;
    asm("{ .reg .u64 t; cvta.to.shared.u64 t, %1; cvt.u32.u64 %0, t; }" : "=r"(a) : "l"(p));
    return a;
}
__device__ __forceinline__ void cp16(uint32_t dst, const void* src, int ok) {
    asm volatile("cp.async.cg.shared.global [%0], [%1], 16, %2;"
                 :: "r"(dst), "l"(src), "r"(ok ? 16 : 0) : "memory");
}
__device__ __forceinline__ void ldm_x4(uint32_t& r0, uint32_t& r1, uint32_t& r2, uint32_t& r3,
                                       uint32_t addr) {
    asm volatile("ldmatrix.sync.aligned.m8n8.x4.shared.b16 {%0,%1,%2,%3}, [%4];"
                 : "=r"(r0), "=r"(r1), "=r"(r2), "=r"(r3) : "r"(addr));
}
__device__ __forceinline__ void ldm_x2(uint32_t& r0, uint32_t& r1, uint32_t addr) {
    asm volatile("ldmatrix.sync.aligned.m8n8.x2.shared.b16 {%0,%1}, [%2];"
                 : "=r"(r0), "=r"(r1) : "r"(addr));
}
__device__ __forceinline__ uint32_t hmul2c(uint32_t a, uint32_t s) {
    uint32_t r;
    asm("mul.f16x2 %0, %1, %2;" : "=r"(r) : "r"(a), "r"(s));
    return r;
}
__device__ __forceinline__ void mma_f16(float* c, uint32_t a0, uint32_t a1, uint32_t a2,
                                        uint32_t a3, uint32_t b0, uint32_t b1) {
    asm volatile(
        "mma.sync.aligned.m16n8k16.row.col.f32.f16.f16.f32 "
        "{%0,%1,%2,%3}, {%4,%5,%6,%7}, {%8,%9}, {%0,%1,%2,%3};"
        : "+f"(c[0]), "+f"(c[1]), "+f"(c[2]), "+f"(c[3])
        : "r"(a0), "r"(a1), "r"(a2), "r"(a3), "r"(b0), "r"(b1));
}

__global__ __launch_bounds__(256, 2) void k_gemm_mma(float* __restrict__ out) {
    extern __shared__ char smem[];
    uint32_t sbase = smem_u32(smem);

    int t    = threadIdx.x;
    int wid  = t >> 5;
    int lane = t & 31;
    int warp_m = wid >> 2;
    int warp_n = wid & 3;
    int bm = blockIdx.x * 128;

    float acc[4][4][4];
    #pragma unroll
    for (int i = 0; i < 4; i++)
        #pragma unroll
        for (int j = 0; j < 4; j++)
            #pragma unroll
            for (int q = 0; q < 4; q++) acc[i][j][q] = 0.f;

    int a_row = warp_m * 64 + (lane & 15);
    int a_kof = (lane >> 4) * 8;
    int b_row = warp_n * 32 + (lane & 7);
    int b_kof = ((lane >> 3) & 1) * 8;

    const char* xh = (const char*)(g_xh + (size_t)bm * K_GEMM);

    int lr[4], lu[4], okA[4];
    #pragma unroll
    for (int p = 0; p < 4; p++) {
        int u = t + p * 256;
        lr[p] = u >> 3;
        lu[p] = u & 7;
        okA[p] = (bm + lr[p]) < N_NODES;
    }

    #define ISSUE(c, st) do {                                                   \
        uint32_t sbuf = sbase + (st) * STAGE_B;                                  \
        _Pragma("unroll")                                                        \
        for (int p = 0; p < 4; p++) {                                            \
            size_t go = ((size_t)lr[p] * K_GEMM + (c) * GBK + lu[p] * 8) * 2;    \
            uint32_t so = (uint32_t)lr[p] * (GAPITCH * 2) + lu[p] * 16;          \
            cp16(sbuf + SM_A  + so, xh + go, okA[p]);                            \
            cp16(sbuf + SM_BH + so, (const char*)g_wt_hi + go, 1);               \
            cp16(sbuf + SM_BL + so, (const char*)g_wt_lo + go, 1);               \
        }                                                                        \
        asm volatile("cp.async.commit_group;" ::: "memory");                     \
    } while (0)

    ISSUE(0, 0);

    for (int c = 0; c < NCHUNK; c++) {
        int st = c & 1;
        if (c + 1 < NCHUNK) {
            ISSUE(c + 1, st ^ 1);
            asm volatile("cp.async.wait_group 1;" ::: "memory");
        } else {
            asm volatile("cp.async.wait_group 0;" ::: "memory");
        }
        __syncthreads();

        uint32_t sb = sbase + st * STAGE_B;
        #pragma unroll
        for (int ks = 0; ks < GBK / 16; ks++) {
            uint32_t bh[4][2], bl[4][2];
            #pragma unroll
            for (int nj = 0; nj < 4; nj++) {
                uint32_t bofs = (uint32_t)(b_row + nj * 8) * (GAPITCH * 2)
                              + (ks * 16 + b_kof) * 2;
                ldm_x2(bh[nj][0], bh[nj][1], sb + SM_BH + bofs);
                ldm_x2(bl[nj][0], bl[nj][1], sb + SM_BL + bofs);
                bl[nj][0] = hmul2c(bl[nj][0], H2_INV64);
                bl[nj][1] = hmul2c(bl[nj][1], H2_INV64);
            }
            uint32_t ah[4][4];
            #pragma unroll
            for (int mi = 0; mi < 4; mi++) {
                uint32_t aofs = (uint32_t)(a_row + mi * 16) * (GAPITCH * 2)
                              + (ks * 16 + a_kof) * 2;
                ldm_x4(ah[mi][0], ah[mi][1], ah[mi][2], ah[mi][3], sb + SM_A + aofs);
            }
            // sweep 1: Xh * Whi
            #pragma unroll
            for (int mi = 0; mi < 4; mi++)
                #pragma unroll
                for (int nj = 0; nj < 4; nj++)
                    mma_f16(acc[mi][nj], ah[mi][0], ah[mi][1], ah[mi][2], ah[mi][3],
                            bh[nj][0], bh[nj][1]);
            // sweep 2: Xh * Wlo
            #pragma unroll
            for (int mi = 0; mi < 4; mi++)
                #pragma unroll
                for (int nj = 0; nj < 4; nj++)
                    mma_f16(acc[mi][nj], ah[mi][0], ah[mi][1], ah[mi][2], ah[mi][3],
                            bl[nj][0], bl[nj][1]);
        }
        __syncthreads();
    }

    // ---- epilogue: + degW, store, BN column partials ----
    float* scol  = (float*)smem;
    float* scolq = (float*)(smem + 512);
    if (t < 128) { scol[t] = 0.f; scolq[t] = 0.f; }
    __syncthreads();

    int gid = lane >> 2;
    int tig = lane & 3;
    float ls[8], lq[8];
    #pragma unroll
    for (int q = 0; q < 8; q++) { ls[q] = 0.f; lq[q] = 0.f; }

    #pragma unroll
    for (int mi = 0; mi < 4; mi++) {
        #pragma unroll
        for (int half = 0; half < 2; half++) {
            int row = bm + warp_m * 64 + mi * 16 + gid + half * 8;
            if (row < N_NODES) {
                int dg = g_deg[row];
                const float* dw = &g_degW[dg * D_OUT];
                #pragma unroll
                for (int nj = 0; nj < 4; nj++) {
                    int col = warp_n * 32 + nj * 8 + tig * 2;
                    float2 v;
                    v.x = acc[mi][nj][half * 2 + 0] + dw[col];
                    v.y = acc[mi][nj][half * 2 + 1] + dw[col + 1];
                    *(float2*)&out[(size_t)row * D_OUT + col] = v;
                    ls[nj * 2 + 0] += v.x;  lq[nj * 2 + 0] = fmaf(v.x, v.x, lq[nj * 2 + 0]);
                    ls[nj * 2 + 1] += v.y;  lq[nj * 2 + 1] = fmaf(v.y, v.y, lq[nj * 2 + 1]);
                }
            }
        }
    }
    #pragma unroll
    for (int nj = 0; nj < 4; nj++) {
        #pragma unroll
        for (int xy = 0; xy < 2; xy++) {
            int col = warp_n * 32 + nj * 8 + tig * 2 + xy;
            atomicAdd(&scol[col],  ls[nj * 2 + xy]);
            atomicAdd(&scolq[col], lq[nj * 2 + xy]);
        }
    }
    __syncthreads();
    if (t < 128) {
        atomicAdd(&g_colsum[t], scol[t]);
        atomicAdd(&g_colsq[t],  scolq[t]);
    }
}

// ------------------------- fused BN finalize + normalize -------------------
__global__ __launch_bounds__(256) void k_normalize(const float* __restrict__ gamma,
                                                   const float* __restrict__ beta,
                                                   float* __restrict__ out) {
    __shared__ float sscale[128], sbias[128];
    if (threadIdx.x < 128) {
        int c = threadIdx.x;
        float inv_n = 1.f / (float)N_NODES;
        float mu  = g_colsum[c] * inv_n;
        float var = g_colsq[c] * inv_n - mu * mu;
        float rstd = rsqrtf(var + EPS_BN);
        float sc = gamma[c] * rstd;
        sscale[c] = sc;
        sbias[c]  = beta[c] - mu * sc;
    }
    __syncthreads();
    int i = blockIdx.x * blockDim.x + threadIdx.x;
    if (i < N_NODES * D_OUT / 4) {
        int c0 = (i & 31) * 4;
        float4 v = ((float4*)out)[i];
        v.x = fmaxf(0.f, fmaf(v.x, sscale[c0 + 0], sbias[c0 + 0]));
        v.y = fmaxf(0.f, fmaf(v.y, sscale[c0 + 1], sbias[c0 + 1]));
        v.z = fmaxf(0.f, fmaf(v.z, sscale[c0 + 2], sbias[c0 + 2]));
        v.w = fmaxf(0.f, fmaf(v.w, sscale[c0 + 3], sbias[c0 + 3]));
        ((float4*)out)[i] = v;
    }
}

// ------------------------- launch -----------------------------------------
extern "C" void kernel_launch(void* const* d_in, const int* in_sizes, int n_in,
                              void* d_out, int out_size) {
    const float* inputs  = (const float*)d_in[0];   // [E, 128]
    const int*   index   = (const int*)  d_in[1];   // [E]
    const float* deg_emb = (const float*)d_in[2];   // [100, 128]
    const float* W       = (const float*)d_in[3];   // [640, 128]
    const float* gamma   = (const float*)d_in[4];   // [128]
    const float* beta    = (const float*)d_in[5];   // [128]
    float* out = (float*)d_out;                     // [50000, 128]

    static cudaStream_t s2 = nullptr;
    static cudaEvent_t ev_fork, ev_prep;
    if (!s2) {
        cudaStreamCreateWithFlags(&s2, cudaStreamNonBlocking);
        cudaEventCreateWithFlags(&ev_fork, cudaEventDisableTiming);
        cudaEventCreateWithFlags(&ev_prep, cudaEventDisableTiming);
        cudaFuncSetAttribute(k_gemm_mma, cudaFuncAttributeMaxDynamicSharedMemorySize,
                             SM_GEMM_TOTAL);
    }

    void* p_counts = nullptr; void* p_colsum = nullptr; void* p_colsq = nullptr;
    void* p_agg = nullptr;
    cudaGetSymbolAddress(&p_counts, g_counts);
    cudaGetSymbolAddress(&p_colsum, g_colsum);
    cudaGetSymbolAddress(&p_colsq,  g_colsq);
    cudaGetSymbolAddress(&p_agg,    g_agg);

    // fork: prep work (memsets + W split/degW) overlaps the CSR build
    cudaEventRecord(ev_fork, 0);
    cudaStreamWaitEvent(s2, ev_fork, 0);
    cudaMemsetAsync(p_colsum, 0, D_OUT * sizeof(float), s2);
    cudaMemsetAsync(p_colsq,  0, D_OUT * sizeof(float), s2);
    k_prep<<<228, 128, 0, s2>>>(deg_emb, W);
    cudaEventRecord(ev_prep, s2);

    // main stream: CSR build + aggregation
    cudaMemsetAsync(p_counts, 0, N_NODES * sizeof(int));
    cudaMemsetAsync(p_agg,    0, SCAN_NBLK * sizeof(int));
    k_hist<<<(E_EDGES / 4 + 255) / 256, 256>>>(index);
    k_scan_onepass<<<SCAN_NBLK, SCAN_BLK>>>();
    k_scatter<<<(E_EDGES / 4 + 255) / 256, 256>>>(index);
    k_agg<<<(N_NODES + 7) / 8, 256>>>(inputs);

    // join: GEMM needs prep outputs
    cudaStreamWaitEvent(0, ev_prep, 0);
    k_gemm_mma<<<GEMM_TILES, 256, SM_GEMM_TOTAL>>>(out);
    k_normalize<<<(N_NODES * D_OUT / 4 + 255) / 256, 256>>>(gamma, beta, out);
}